// round 11
// baseline (speedup 1.0000x reference)
#include <cuda_runtime.h>
#include <cstdint>

// ---------------- config ----------------
#define CTAS        1024
#define THREADS     256              // 8 warps = 4 pairs; pair owns 256 rows
#define STAGE_ROWS  32
#define STAGE_BYTES 8192
#define RING        2
#define NSTAGES     8                // 1024 CTAs * 4 pairs * 8 * 32 rows = 2^20
#define ROWS_CTA    1024

// smem layout (bytes)
#define FB_BYTES    16384            // tf32 W [n][k]; reused as ps[2][1024]
#define SMEM_RING   FB_BYTES
#define RING_PAIR   (RING * STAGE_BYTES)             // 16384 per pair
#define SMEM_TOTAL  (FB_BYTES + 4 * RING_PAIR)       // 81920 -> 2 CTA/SM

// ---------------- math constants ----------------
#define C_SCALE_L2E  4.3280851227f   // 3 * log2(e)
#define C_CLAMP_L2E 14.4269504089f   // 10 * log2(e)
#define C_LN2        0.6931471806f

// ---------------- helpers ----------------
static __device__ __forceinline__ uint32_t smem_u32(const void* p) {
    uint32_t a;
    asm("{ .reg .u64 t; cvta.to.shared.u64 t, %1; cvt.u32.u64 %0, t; }"
        : "=r"(a) : "l"(p));
    return a;
}
static __device__ __forceinline__ void cp16(uint32_t s, const void* g) {
    asm volatile("cp.async.cg.shared.global [%0], [%1], 16;" :: "r"(s), "l"(g));
}
#define CP_COMMIT() asm volatile("cp.async.commit_group;" ::: "memory")
#define CP_WAIT(n)  asm volatile("cp.async.wait_group %0;" :: "n"(n) : "memory")
#define PAIR_BAR(id) asm volatile("bar.sync %0, 64;" :: "r"(id) : "memory")

static __device__ __forceinline__ float exp2_fast(float x) {
    float r; asm("ex2.approx.ftz.f32 %0, %1;" : "=f"(r) : "f"(x)); return r;
}
static __device__ __forceinline__ float lg2_fast(float x) {
    float r; asm("lg2.approx.f32 %0, %1;" : "=f"(r) : "f"(x)); return r;
}
static __device__ __forceinline__ float rcp_fast(float x) {
    float r; asm("rcp.approx.ftz.f32 %0, %1;" : "=f"(r) : "f"(x)); return r;
}
static __device__ __forceinline__ uint32_t f2tf32(float v) {
    uint32_t r; asm("cvt.rna.tf32.f32 %0, %1;" : "=r"(r) : "f"(v)); return r;
}
static __device__ __forceinline__ uint32_t lds32(const char* smem, uint32_t off) {
    return *reinterpret_cast<const uint32_t*>(smem + off);
}

// mma.sync m16n8k8 tf32
static __device__ __forceinline__ void mma_tf32(
    float* d, uint32_t a0, uint32_t a1, uint32_t a2, uint32_t a3,
    uint32_t b0, uint32_t b1) {
    asm volatile(
        "mma.sync.aligned.m16n8k8.row.col.f32.tf32.tf32.f32 "
        "{%0,%1,%2,%3}, {%4,%5,%6,%7}, {%8,%9}, {%0,%1,%2,%3};"
        : "+f"(d[0]), "+f"(d[1]), "+f"(d[2]), "+f"(d[3])
        : "r"(a0), "r"(a1), "r"(a2), "r"(a3), "r"(b0), "r"(b1));
}

static __device__ __forceinline__ float expv(float z) {
    float w = fminf(fmaxf(z * C_SCALE_L2E, -C_CLAMP_L2E), C_CLAMP_L2E);
    return exp2_fast(w);
}
// mish(ln s): e^(ln s) == s exactly -> tanh(softplus) = ((1+s)^2-1)/((1+s)^2+1)
static __device__ __forceinline__ float mish_of_ln(float s) {
    float lse = C_LN2 * lg2_fast(s);
    float up  = s + 1.0f;
    float q   = up * up;
    return lse * (q - 1.0f) * rcp_fast(q + 1.0f);
}

// load HALF a stage: 16 rows (4 KB contiguous in gmem) at stage-local row off16,
// XOR-swizzled dst (R3-proven pattern; (off16 + r) & 7 == r & 7 since off16 in {0,16})
static __device__ __forceinline__ void load_half(
    uint32_t stage_base, int off16, const float* __restrict__ src, int lane) {
#pragma unroll
    for (int i = 0; i < 8; i++) {
        int idx = i * 32 + lane;            // 256 16B-chunks
        int r = idx >> 4, c = idx & 15;
        cp16(stage_base + (uint32_t)((off16 + r) * 256 + ((c ^ (r & 7)) << 4)),
             src + (size_t)idx * 4);
    }
}

// ---------------- kernel ----------------
__global__ void __launch_bounds__(THREADS, 2) fused_lin_lse_mish(
    const float* __restrict__ x, const float* __restrict__ W,
    float* __restrict__ out) {
    extern __shared__ char smem[];
    const uint32_t sb = smem_u32(smem);
    const int tid  = threadIdx.x;
    const int lane = tid & 31;
    const int w    = tid >> 5;
    const int h    = w & 1;              // column half: cols 32h .. 32h+31
    const int pair = w >> 1;             // 0..3 -> rows pair*256 .. +255
    const int g    = lane >> 2;          // 0..7
    const int t    = lane & 3;           // 0..3
    const int barid = 1 + pair;

    const size_t crow0 = (size_t)blockIdx.x * ROWS_CTA;
    const size_t prow0 = crow0 + (size_t)pair * (NSTAGES * STAGE_ROWS);
    const uint32_t ring = sb + SMEM_RING + (uint32_t)pair * RING_PAIR;
    const int off16 = h * 16;            // my half-rows within each stage

    // ---- prologue: co-load stages 0,1 (each warp its 16-row half) ----
#pragma unroll
    for (int s = 0; s < RING; s++) {
        load_half(ring + (uint32_t)s * STAGE_BYTES, off16,
                  x + (prow0 + (size_t)(s * STAGE_ROWS + off16)) * 64, lane);
        CP_COMMIT();
    }

    // ---- stage W once (tf32) ----
    uint32_t* FB = reinterpret_cast<uint32_t*>(smem);
#pragma unroll
    for (int i = 0; i < 16; i++)
        FB[i * THREADS + tid] = f2tf32(W[i * THREADS + tid]);
    __syncthreads();

    // ---- permanent B fragments for half h (nb-blocks 4h..4h+3) ----
    uint32_t b[8][4][2];                 // [kb][nb][b0,b1]
#pragma unroll
    for (int kb = 0; kb < 8; kb++)
#pragma unroll
        for (int nb = 0; nb < 4; nb++) {
            int n = 32 * h + 8 * nb + g;
            b[kb][nb][0] = FB[n * 64 + 8 * kb + t];
            b[kb][nb][1] = FB[n * 64 + 8 * kb + 4 + t];
        }
    __syncthreads();                     // FB done -> region becomes ps[2][1024]
    float* ps = reinterpret_cast<float*>(smem);

#pragma unroll
    for (int s = 0; s < NSTAGES; s++) {
        CP_WAIT(1);                      // my half of stage s resident
        PAIR_BAR(barid);                 // partner's half too (it waited as well)

        const char* As = smem + SMEM_RING + (size_t)pair * RING_PAIR
                       + (size_t)(s & 1) * STAGE_BYTES;

        float acc[2][4][4];
#pragma unroll
        for (int mt = 0; mt < 2; mt++)
#pragma unroll
            for (int nb = 0; nb < 4; nb++)
#pragma unroll
                for (int q = 0; q < 4; q++) acc[mt][nb][q] = 0.0f;

#pragma unroll
        for (int kb = 0; kb < 8; kb++) {
            const uint32_t cx0 = (uint32_t)((((2 * kb) ^ g) << 4)) + (uint32_t)(t * 4);
            const uint32_t cx1 = (uint32_t)((((2 * kb + 1) ^ g) << 4)) + (uint32_t)(t * 4);
#pragma unroll
            for (int mt = 0; mt < 2; mt++) {
                const uint32_t rlo = (uint32_t)((mt * 16 + g) * 256);
                uint32_t a0 = lds32(As, rlo + cx0);
                uint32_t a1 = lds32(As, rlo + 8 * 256 + cx0);
                uint32_t a2 = lds32(As, rlo + cx1);
                uint32_t a3 = lds32(As, rlo + 8 * 256 + cx1);
#pragma unroll
                for (int nb = 0; nb < 4; nb++)
                    mma_tf32(acc[mt][nb], a0, a1, a2, a3,
                             b[kb][nb][0], b[kb][nb][1]);
            }
        }

        PAIR_BAR(barid);                 // both consumed stage s -> buffer reusable

        // ---- refill buffer (s&1) with stage s+2 (my half) ----
        if (s + RING < NSTAGES)
            load_half(ring + (uint32_t)(s & 1) * STAGE_BYTES, off16,
                      x + (prow0 + (size_t)((s + RING) * STAGE_ROWS + off16)) * 64,
                      lane);
        CP_COMMIT();                     // uniform accounting (empty ok)

        // ---- partial sums (overlaps with in-flight loads) ----
#pragma unroll
        for (int mt = 0; mt < 2; mt++) {
            float sl = 0.0f, sh = 0.0f;
#pragma unroll
            for (int nb = 0; nb < 4; nb++) {
                sl += expv(acc[mt][nb][0]) + expv(acc[mt][nb][1]);
                sh += expv(acc[mt][nb][2]) + expv(acc[mt][nb][3]);
            }
            sl += __shfl_xor_sync(0xFFFFFFFF, sl, 1);
            sl += __shfl_xor_sync(0xFFFFFFFF, sl, 2);
            sh += __shfl_xor_sync(0xFFFFFFFF, sh, 1);
            sh += __shfl_xor_sync(0xFFFFFFFF, sh, 2);
            if (t == 0) {
                int loc = pair * 256 + s * STAGE_ROWS + mt * 16 + g;
                ps[h * 1024 + loc]     = sl;
                ps[h * 1024 + loc + 8] = sh;
            }
        }
    }

    // ---- combine halves + mish (single block sync) ----
    __syncthreads();
#pragma unroll
    for (int rep = 0; rep < 4; rep++) {
        int r = rep * THREADS + tid;
        float sfull = ps[r] + ps[1024 + r];
        out[crow0 + r] = mish_of_ln(sfull);
    }
}

// ---------------- launch ----------------
extern "C" void kernel_launch(void* const* d_in, const int* in_sizes, int n_in,
                              void* d_out, int out_size) {
    (void)in_sizes; (void)n_in; (void)out_size;
    const float* x = (const float*)d_in[0];
    const float* W = (const float*)d_in[1];
    float* out = (float*)d_out;

    cudaFuncSetAttribute(fused_lin_lse_mish,
                         cudaFuncAttributeMaxDynamicSharedMemorySize, SMEM_TOTAL);
    fused_lin_lse_mish<<<CTAS, THREADS, SMEM_TOTAL>>>(x, W, out);
}

// round 12
// speedup vs baseline: 1.0097x; 1.0097x over previous
#include <cuda_runtime.h>
#include <cstdint>

// ---------------- config ----------------
#define CTAS        1024
#define THREADS     256              // 8 warps = 4 pairs; pair owns 256 rows
#define STAGE_ROWS  32
#define STAGE_BYTES 8192
#define RING        2
#define NSTAGES     8                // 1024 CTAs * 4 pairs * 8 * 32 rows = 2^20
#define ROWS_CTA    1024

// smem layout (bytes)
#define FB_BYTES    16384            // tf32 W [n][k]; reused as ps[2][1024]
#define SMEM_RING   FB_BYTES
#define RING_PAIR   (RING * STAGE_BYTES)             // 16384 per pair
#define SMEM_TOTAL  (FB_BYTES + 4 * RING_PAIR)       // 81920 -> 2 CTA/SM

// ---------------- math constants ----------------
#define C_SCALE_L2E  4.3280851227f   // 3 * log2(e)
#define C_CLAMP_L2E 14.4269504089f   // 10 * log2(e)
#define C_LN2        0.6931471806f

// ---------------- helpers ----------------
static __device__ __forceinline__ uint32_t smem_u32(const void* p) {
    uint32_t a;
    asm("{ .reg .u64 t; cvta.to.shared.u64 t, %1; cvt.u32.u64 %0, t; }"
        : "=r"(a) : "l"(p));
    return a;
}
static __device__ __forceinline__ void cp16(uint32_t s, const void* g) {
    asm volatile("cp.async.cg.shared.global [%0], [%1], 16;" :: "r"(s), "l"(g));
}
#define CP_COMMIT() asm volatile("cp.async.commit_group;" ::: "memory")
#define CP_WAIT(n)  asm volatile("cp.async.wait_group %0;" :: "n"(n) : "memory")
#define PAIR_BAR(id) asm volatile("bar.sync %0, 64;" :: "r"(id) : "memory")

static __device__ __forceinline__ float exp2_fast(float x) {
    float r; asm("ex2.approx.ftz.f32 %0, %1;" : "=f"(r) : "f"(x)); return r;
}
static __device__ __forceinline__ float lg2_fast(float x) {
    float r; asm("lg2.approx.f32 %0, %1;" : "=f"(r) : "f"(x)); return r;
}
static __device__ __forceinline__ float rcp_fast(float x) {
    float r; asm("rcp.approx.ftz.f32 %0, %1;" : "=f"(r) : "f"(x)); return r;
}
static __device__ __forceinline__ uint32_t f2tf32(float v) {
    uint32_t r; asm("cvt.rna.tf32.f32 %0, %1;" : "=r"(r) : "f"(v)); return r;
}
static __device__ __forceinline__ uint32_t lds32(const char* smem, uint32_t off) {
    return *reinterpret_cast<const uint32_t*>(smem + off);
}

// mma.sync m16n8k8 tf32
static __device__ __forceinline__ void mma_tf32(
    float* d, uint32_t a0, uint32_t a1, uint32_t a2, uint32_t a3,
    uint32_t b0, uint32_t b1) {
    asm volatile(
        "mma.sync.aligned.m16n8k8.row.col.f32.tf32.tf32.f32 "
        "{%0,%1,%2,%3}, {%4,%5,%6,%7}, {%8,%9}, {%0,%1,%2,%3};"
        : "+f"(d[0]), "+f"(d[1]), "+f"(d[2]), "+f"(d[3])
        : "r"(a0), "r"(a1), "r"(a2), "r"(a3), "r"(b0), "r"(b1));
}

static __device__ __forceinline__ float expv(float z) {
    float w = fminf(fmaxf(z * C_SCALE_L2E, -C_CLAMP_L2E), C_CLAMP_L2E);
    return exp2_fast(w);
}
// mish(ln s): e^(ln s) == s exactly -> tanh(softplus) = ((1+s)^2-1)/((1+s)^2+1)
static __device__ __forceinline__ float mish_of_ln(float s) {
    float lse = C_LN2 * lg2_fast(s);
    float up  = s + 1.0f;
    float q   = up * up;
    return lse * (q - 1.0f) * rcp_fast(q + 1.0f);
}

// load HALF a stage: 16 rows (4 KB contiguous in gmem) at stage-local row off16,
// XOR-swizzled dst (R3-proven pattern; (off16 + r) & 7 == r & 7 since off16 in {0,16})
static __device__ __forceinline__ void load_half(
    uint32_t stage_base, int off16, const float* __restrict__ src, int lane) {
#pragma unroll
    for (int i = 0; i < 8; i++) {
        int idx = i * 32 + lane;            // 256 16B-chunks
        int r = idx >> 4, c = idx & 15;
        cp16(stage_base + (uint32_t)((off16 + r) * 256 + ((c ^ (r & 7)) << 4)),
             src + (size_t)idx * 4);
    }
}

// ---------------- kernel ----------------
__global__ void __launch_bounds__(THREADS, 2) fused_lin_lse_mish(
    const float* __restrict__ x, const float* __restrict__ W,
    float* __restrict__ out) {
    extern __shared__ char smem[];
    const uint32_t sb = smem_u32(smem);
    const int tid  = threadIdx.x;
    const int lane = tid & 31;
    const int w    = tid >> 5;
    const int h    = w & 1;              // column half: cols 32h .. 32h+31
    const int pair = w >> 1;             // 0..3 -> rows pair*256 .. +255
    const int g    = lane >> 2;          // 0..7
    const int t    = lane & 3;           // 0..3
    const int barid = 1 + pair;

    const size_t crow0 = (size_t)blockIdx.x * ROWS_CTA;
    const size_t prow0 = crow0 + (size_t)pair * (NSTAGES * STAGE_ROWS);
    const uint32_t ring = sb + SMEM_RING + (uint32_t)pair * RING_PAIR;
    const int off16 = h * 16;            // my half-rows within each stage

    // ---- prologue: co-load stages 0,1 (each warp its 16-row half) ----
#pragma unroll
    for (int s = 0; s < RING; s++) {
        load_half(ring + (uint32_t)s * STAGE_BYTES, off16,
                  x + (prow0 + (size_t)(s * STAGE_ROWS + off16)) * 64, lane);
        CP_COMMIT();
    }

    // ---- stage W once (tf32) ----
    uint32_t* FB = reinterpret_cast<uint32_t*>(smem);
#pragma unroll
    for (int i = 0; i < 16; i++)
        FB[i * THREADS + tid] = f2tf32(W[i * THREADS + tid]);
    __syncthreads();

    // ---- permanent B fragments for half h (nb-blocks 4h..4h+3) ----
    uint32_t b[8][4][2];                 // [kb][nb][b0,b1]
#pragma unroll
    for (int kb = 0; kb < 8; kb++)
#pragma unroll
        for (int nb = 0; nb < 4; nb++) {
            int n = 32 * h + 8 * nb + g;
            b[kb][nb][0] = FB[n * 64 + 8 * kb + t];
            b[kb][nb][1] = FB[n * 64 + 8 * kb + 4 + t];
        }
    __syncthreads();                     // FB done -> region becomes ps[2][1024]
    float* ps = reinterpret_cast<float*>(smem);

#pragma unroll
    for (int s = 0; s < NSTAGES; s++) {
        CP_WAIT(1);                      // my half of stage s resident
        PAIR_BAR(barid);                 // partner's half too (it waited as well)

        const char* As = smem + SMEM_RING + (size_t)pair * RING_PAIR
                       + (size_t)(s & 1) * STAGE_BYTES;

        float acc[2][4][4];
#pragma unroll
        for (int mt = 0; mt < 2; mt++)
#pragma unroll
            for (int nb = 0; nb < 4; nb++)
#pragma unroll
                for (int q = 0; q < 4; q++) acc[mt][nb][q] = 0.0f;

#pragma unroll
        for (int kb = 0; kb < 8; kb++) {
            const uint32_t cx0 = (uint32_t)((((2 * kb) ^ g) << 4)) + (uint32_t)(t * 4);
            const uint32_t cx1 = (uint32_t)((((2 * kb + 1) ^ g) << 4)) + (uint32_t)(t * 4);
#pragma unroll
            for (int mt = 0; mt < 2; mt++) {
                const uint32_t rlo = (uint32_t)((mt * 16 + g) * 256);
                uint32_t a0 = lds32(As, rlo + cx0);
                uint32_t a1 = lds32(As, rlo + 8 * 256 + cx0);
                uint32_t a2 = lds32(As, rlo + cx1);
                uint32_t a3 = lds32(As, rlo + 8 * 256 + cx1);
#pragma unroll
                for (int nb = 0; nb < 4; nb++)
                    mma_tf32(acc[mt][nb], a0, a1, a2, a3,
                             b[kb][nb][0], b[kb][nb][1]);
            }
        }

        PAIR_BAR(barid);                 // both consumed stage s -> buffer reusable

        // ---- refill buffer (s&1) with stage s+2 (my half) ----
        if (s + RING < NSTAGES)
            load_half(ring + (uint32_t)(s & 1) * STAGE_BYTES, off16,
                      x + (prow0 + (size_t)((s + RING) * STAGE_ROWS + off16)) * 64,
                      lane);
        CP_COMMIT();                     // uniform accounting (empty ok)

        // ---- partial sums (overlaps with in-flight loads) ----
#pragma unroll
        for (int mt = 0; mt < 2; mt++) {
            float sl = 0.0f, sh = 0.0f;
#pragma unroll
            for (int nb = 0; nb < 4; nb++) {
                sl += expv(acc[mt][nb][0]) + expv(acc[mt][nb][1]);
                sh += expv(acc[mt][nb][2]) + expv(acc[mt][nb][3]);
            }
            sl += __shfl_xor_sync(0xFFFFFFFF, sl, 1);
            sl += __shfl_xor_sync(0xFFFFFFFF, sl, 2);
            sh += __shfl_xor_sync(0xFFFFFFFF, sh, 1);
            sh += __shfl_xor_sync(0xFFFFFFFF, sh, 2);
            if (t == 0) {
                int loc = pair * 256 + s * STAGE_ROWS + mt * 16 + g;
                ps[h * 1024 + loc]     = sl;
                ps[h * 1024 + loc + 8] = sh;
            }
        }
    }

    // ---- combine halves + mish (single block sync) ----
    __syncthreads();
#pragma unroll
    for (int rep = 0; rep < 4; rep++) {
        int r = rep * THREADS + tid;
        float sfull = ps[r] + ps[1024 + r];
        out[crow0 + r] = mish_of_ln(sfull);
    }
}

// ---------------- launch ----------------
extern "C" void kernel_launch(void* const* d_in, const int* in_sizes, int n_in,
                              void* d_out, int out_size) {
    (void)in_sizes; (void)n_in; (void)out_size;
    const float* x = (const float*)d_in[0];
    const float* W = (const float*)d_in[1];
    float* out = (float*)d_out;

    cudaFuncSetAttribute(fused_lin_lse_mish,
                         cudaFuncAttributeMaxDynamicSharedMemorySize, SMEM_TOTAL);
    fused_lin_lse_mish<<<CTAS, THREADS, SMEM_TOTAL>>>(x, W, out);
}

// round 13
// speedup vs baseline: 1.3022x; 1.2896x over previous
#include <cuda_runtime.h>
#include <cstdint>

// ---------------- config ----------------
#define CTAS        1024
#define THREADS     256              // 8 warps, each fully independent
#define UNIT_ROWS   32
#define UNIT_BYTES  8192
#define NSLOTS      2
#define NUNITS      4                // 8 warps * 4 * 32 rows * 1024 CTAs = 2^20
#define ROWS_CTA    1024

// smem: FB (fragment-major tf32 W, 16 KB) + per-warp 2-slot rings
#define FB_BYTES    16384
#define SMEM_X      FB_BYTES
#define SMEM_TOTAL  (FB_BYTES + 8 * NSLOTS * UNIT_BYTES)   // 147456 -> 1 CTA/SM, 256 regs/thr

// ---------------- math constants ----------------
#define C_SCALE_L2E  4.3280851227f   // 3 * log2(e)
#define C_CLAMP_L2E 14.4269504089f   // 10 * log2(e)
#define C_LN2        0.6931471806f

// ---------------- helpers ----------------
static __device__ __forceinline__ uint32_t smem_u32(const void* p) {
    uint32_t a;
    asm("{ .reg .u64 t; cvta.to.shared.u64 t, %1; cvt.u32.u64 %0, t; }"
        : "=r"(a) : "l"(p));
    return a;
}
static __device__ __forceinline__ void cp16(uint32_t s, const void* g) {
    asm volatile("cp.async.cg.shared.global [%0], [%1], 16;" :: "r"(s), "l"(g));
}
#define CP_COMMIT() asm volatile("cp.async.commit_group;" ::: "memory")
#define CP_WAIT1()  asm volatile("cp.async.wait_group 1;" ::: "memory")

static __device__ __forceinline__ float exp2_fast(float x) {
    float r; asm("ex2.approx.ftz.f32 %0, %1;" : "=f"(r) : "f"(x)); return r;
}
static __device__ __forceinline__ float lg2_fast(float x) {
    float r; asm("lg2.approx.f32 %0, %1;" : "=f"(r) : "f"(x)); return r;
}
static __device__ __forceinline__ float rcp_fast(float x) {
    float r; asm("rcp.approx.ftz.f32 %0, %1;" : "=f"(r) : "f"(x)); return r;
}
static __device__ __forceinline__ uint32_t f2tf32(float v) {
    uint32_t r; asm("cvt.rna.tf32.f32 %0, %1;" : "=r"(r) : "f"(v)); return r;
}
static __device__ __forceinline__ uint32_t lds32(const char* smem, uint32_t off) {
    return *reinterpret_cast<const uint32_t*>(smem + off);
}

// mma.sync m16n8k8 tf32
static __device__ __forceinline__ void mma_tf32(
    float* d, uint32_t a0, uint32_t a1, uint32_t a2, uint32_t a3,
    uint32_t b0, uint32_t b1) {
    asm volatile(
        "mma.sync.aligned.m16n8k8.row.col.f32.tf32.tf32.f32 "
        "{%0,%1,%2,%3}, {%4,%5,%6,%7}, {%8,%9}, {%0,%1,%2,%3};"
        : "+f"(d[0]), "+f"(d[1]), "+f"(d[2]), "+f"(d[3])
        : "r"(a0), "r"(a1), "r"(a2), "r"(a3), "r"(b0), "r"(b1));
}

static __device__ __forceinline__ float expv(float z) {
    float w = fminf(fmaxf(z * C_SCALE_L2E, -C_CLAMP_L2E), C_CLAMP_L2E);
    return exp2_fast(w);
}
// mish(ln s): e^(ln s) == s exactly -> tanh(softplus) = ((1+s)^2-1)/((1+s)^2+1)
static __device__ __forceinline__ float mish_of_ln(float s) {
    float lse = C_LN2 * lg2_fast(s);
    float up  = s + 1.0f;
    float q   = up * up;
    return lse * (q - 1.0f) * rcp_fast(q + 1.0f);
}

// load one 32-row unit (8 KB contiguous in gmem), XOR-swizzled dst (R3 pattern)
static __device__ __forceinline__ void load_unit(
    uint32_t dst_base, const float* __restrict__ src, int lane) {
#pragma unroll
    for (int i = 0; i < 16; i++) {
        int idx = i * 32 + lane;            // 512 16B-chunks
        int r = idx >> 4, c = idx & 15;
        cp16(dst_base + (uint32_t)(r * 256 + ((c ^ (r & 7)) << 4)),
             src + (size_t)idx * 4);
    }
}

// ---------------- kernel ----------------
__global__ void __launch_bounds__(THREADS, 1) fused_lin_lse_mish(
    const float* __restrict__ x, const float* __restrict__ W,
    float* __restrict__ out) {
    extern __shared__ char smem[];
    const uint32_t sb = smem_u32(smem);
    const int tid  = threadIdx.x;
    const int lane = tid & 31;
    const int w    = tid >> 5;
    const int g    = lane >> 2;          // 0..7
    const int t    = lane & 3;           // 0..3

    const size_t wrow0 = (size_t)blockIdx.x * ROWS_CTA
                       + (size_t)w * (NUNITS * UNIT_ROWS);
    const uint32_t ring = sb + SMEM_X + (uint32_t)w * (NSLOTS * UNIT_BYTES);

    // ---- prologue: fill both slots (DRAM starts immediately) ----
#pragma unroll
    for (int s = 0; s < NSLOTS; s++) {
        load_unit(ring + (uint32_t)s * UNIT_BYTES,
                  x + (wrow0 + (size_t)s * UNIT_ROWS) * 64, lane);
        CP_COMMIT();
    }

    // ---- build fragment-major W (FB): entry e=(kb*4+j)*32+lane holds
    //      {b[2j][0], b[2j][1], b[2j+1][0], b[2j+1][1]} for that lane (R5-verified)
#pragma unroll
    for (int i = 0; i < 4; i++) {
        int e  = i * THREADS + tid;       // 1024 entries
        int el = e & 31, j = (e >> 5) & 3, kb = e >> 7;
        int eg = el >> 2, et = el & 3;
        int n0 = 16 * j + eg, n1 = n0 + 8;
        int k0 = 8 * kb + et;
        uint4 v;
        v.x = f2tf32(W[n0 * 64 + k0]);
        v.y = f2tf32(W[n0 * 64 + k0 + 4]);
        v.z = f2tf32(W[n1 * 64 + k0]);
        v.w = f2tf32(W[n1 * 64 + k0 + 4]);
        *reinterpret_cast<uint4*>(smem + e * 16) = v;
    }
    __syncthreads();                      // only block-wide sync in the kernel

    const uint32_t tq = (uint32_t)(t * 4);

#pragma unroll
    for (int u = 0; u < NUNITS; u++) {
        CP_WAIT1();                       // unit u resident (this warp's own loads)

        const char* As = smem + SMEM_X + (size_t)w * (NSLOTS * UNIT_BYTES)
                       + (size_t)(u & 1) * UNIT_BYTES;

        float acc[2][8][4];
#pragma unroll
        for (int mt = 0; mt < 2; mt++)
#pragma unroll
            for (int nb = 0; nb < 8; nb++)
#pragma unroll
                for (int q = 0; q < 4; q++) acc[mt][nb][q] = 0.0f;

#pragma unroll
        for (int kb = 0; kb < 8; kb++) {
            const uint32_t cx0 = (uint32_t)((((2 * kb) ^ g) << 4)) + tq;
            const uint32_t cx1 = (uint32_t)((((2 * kb + 1) ^ g) << 4)) + tq;

            // B fragments: 4x LDS.128 from FB
            uint32_t b[8][2];
#pragma unroll
            for (int j = 0; j < 4; j++) {
                uint4 bv = *reinterpret_cast<const uint4*>(
                    smem + ((kb * 4 + j) * 32 + lane) * 16);
                b[2 * j][0]     = bv.x;
                b[2 * j][1]     = bv.y;
                b[2 * j + 1][0] = bv.z;
                b[2 * j + 1][1] = bv.w;
            }
#pragma unroll
            for (int mt = 0; mt < 2; mt++) {
                const uint32_t rlo = (uint32_t)((mt * 16 + g) * 256);
                uint32_t a0 = lds32(As, rlo + cx0);
                uint32_t a1 = lds32(As, rlo + 8 * 256 + cx0);
                uint32_t a2 = lds32(As, rlo + cx1);
                uint32_t a3 = lds32(As, rlo + 8 * 256 + cx1);
#pragma unroll
                for (int nb = 0; nb < 8; nb++)
                    mma_tf32(acc[mt][nb], a0, a1, a2, a3, b[nb][0], b[nb][1]);
            }
        }

        // ---- epilogue: full 64-col row sums, fully in-warp (R3-style) ----
#pragma unroll
        for (int mt = 0; mt < 2; mt++) {
            float sl = 0.0f, sh = 0.0f;
#pragma unroll
            for (int nb = 0; nb < 8; nb++) {
                sl += expv(acc[mt][nb][0]) + expv(acc[mt][nb][1]);
                sh += expv(acc[mt][nb][2]) + expv(acc[mt][nb][3]);
            }
            sl += __shfl_xor_sync(0xFFFFFFFF, sl, 1);
            sl += __shfl_xor_sync(0xFFFFFFFF, sl, 2);
            sh += __shfl_xor_sync(0xFFFFFFFF, sh, 1);
            sh += __shfl_xor_sync(0xFFFFFFFF, sh, 2);
            if (t == 0) {
                size_t row = wrow0 + (size_t)u * UNIT_ROWS + mt * 16 + g;
                out[row]     = mish_of_ln(sl);
                out[row + 8] = mish_of_ln(sh);
            }
        }

        // ---- refill the slot just consumed (warp-private, zero coupling) ----
        if (u + NSLOTS < NUNITS)
            load_unit(ring + (uint32_t)(u & 1) * UNIT_BYTES,
                      x + (wrow0 + (size_t)(u + NSLOTS) * UNIT_ROWS) * 64, lane);
        CP_COMMIT();                      // uniform group accounting (empty ok)
    }
}

// ---------------- launch ----------------
extern "C" void kernel_launch(void* const* d_in, const int* in_sizes, int n_in,
                              void* d_out, int out_size) {
    (void)in_sizes; (void)n_in; (void)out_size;
    const float* x = (const float*)d_in[0];
    const float* W = (const float*)d_in[1];
    float* out = (float*)d_out;

    cudaFuncSetAttribute(fused_lin_lse_mish,
                         cudaFuncAttributeMaxDynamicSharedMemorySize, SMEM_TOTAL);
    fused_lin_lse_mish<<<CTAS, THREADS, SMEM_TOTAL>>>(x, W, out);
}